// round 1
// baseline (speedup 1.0000x reference)
#include <cuda_runtime.h>
#include <cuda_bf16.h>

// SudokuDigitsDoubles — exact boolean reduction of the reference pipeline.
//
// Per (puzzle b, row r):
//   m[c]   = 9-bit candidate mask of cell c               (mask[b,d,r,c] > 0.5)
//   pv[c]  = m[c] if popcount(m[c]) == 2 else 0           ("cell is a naked pair")
//   active pattern p: appears exactly twice among pv[0..8]
//   erase[c] = OR of active patterns p with p != pv[c]
//   out bit (d,c) = m[c] & ~erase[c]
//
// All reference intermediates are small integers (input is exactly 0/1),
// so this integer formulation reproduces the float reference bit-exactly.

static constexpr int PUZ_ELEMS = 729;       // 9 digits * 9 rows * 9 cols
static constexpr int PUZ_PER_BLOCK = 8;     // 8 * 729 * 4B = 23328 B smem
static constexpr int THREADS = 256;

__global__ __launch_bounds__(THREADS)
void sudoku_doubles_kernel(const float* __restrict__ in,
                           float* __restrict__ out,
                           int nPuz)
{
    __shared__ float tile[PUZ_PER_BLOCK * PUZ_ELEMS];

    const int basePuz = blockIdx.x * PUZ_PER_BLOCK;
    const int puzCount = min(PUZ_PER_BLOCK, nPuz - basePuz);
    const size_t gbase = (size_t)basePuz * PUZ_ELEMS;

    // ---- coalesced load (float4 on full blocks) ----
    if (puzCount == PUZ_PER_BLOCK) {
        const float4* gin = reinterpret_cast<const float4*>(in + gbase);
        float4* s4 = reinterpret_cast<float4*>(tile);
        #pragma unroll 2
        for (int i = threadIdx.x; i < (PUZ_PER_BLOCK * PUZ_ELEMS) / 4; i += THREADS)
            s4[i] = gin[i];
    } else {
        const float* g = in + gbase;
        const int nElem = puzCount * PUZ_ELEMS;
        for (int i = threadIdx.x; i < nElem; i += THREADS)
            tile[i] = g[i];
    }
    __syncthreads();

    // ---- per-row compute (in-place in smem; rows own disjoint entries) ----
    const int t = threadIdx.x;
    if (t < puzCount * 9) {
        const int pl = t / 9;       // local puzzle
        const int r  = t % 9;       // row
        float* cellBase = tile + pl * PUZ_ELEMS + r * 9;

        // candidate bitmasks per cell
        int m[9];
        #pragma unroll
        for (int c = 0; c < 9; c++) {
            int mm = 0;
            #pragma unroll
            for (int d = 0; d < 9; d++)
                mm |= (cellBase[d * 81 + c] > 0.5f) ? (1 << d) : 0;
            m[c] = mm;
        }

        // naked-pair pattern per cell (0 if not exactly-2 candidates)
        int pv[9];
        #pragma unroll
        for (int c = 0; c < 9; c++)
            pv[c] = (__popc(m[c]) == 2) ? m[c] : 0;

        // occurrence count of each cell's pattern within the row
        int cnt[9];
        #pragma unroll
        for (int j = 0; j < 9; j++) {
            int cc = 0;
            #pragma unroll
            for (int k = 0; k < 9; k++)
                cc += (pv[k] == pv[j]) ? 1 : 0;
            cnt[j] = (pv[j] != 0) ? cc : 0;
        }

        // erase + writeback
        #pragma unroll
        for (int c = 0; c < 9; c++) {
            int e = 0;
            #pragma unroll
            for (int j = 0; j < 9; j++)
                if (cnt[j] == 2 && pv[j] != pv[c]) e |= pv[j];
            const int keep = m[c] & ~e;
            #pragma unroll
            for (int d = 0; d < 9; d++)
                cellBase[d * 81 + c] = (float)((keep >> d) & 1);
        }
    }
    __syncthreads();

    // ---- coalesced store ----
    if (puzCount == PUZ_PER_BLOCK) {
        float4* gout = reinterpret_cast<float4*>(out + gbase);
        const float4* s4 = reinterpret_cast<const float4*>(tile);
        #pragma unroll 2
        for (int i = threadIdx.x; i < (PUZ_PER_BLOCK * PUZ_ELEMS) / 4; i += THREADS)
            gout[i] = s4[i];
    } else {
        float* g = out + gbase;
        const int nElem = puzCount * PUZ_ELEMS;
        for (int i = threadIdx.x; i < nElem; i += THREADS)
            g[i] = tile[i];
    }
}

extern "C" void kernel_launch(void* const* d_in, const int* in_sizes, int n_in,
                              void* d_out, int out_size)
{
    const float* mask = (const float*)d_in[0];
    float* out = (float*)d_out;
    const int nPuz = in_sizes[0] / PUZ_ELEMS;   // 32768
    const int grid = (nPuz + PUZ_PER_BLOCK - 1) / PUZ_PER_BLOCK;
    sudoku_doubles_kernel<<<grid, THREADS>>>(mask, out, nPuz);
}

// round 2
// speedup vs baseline: 1.0455x; 1.0455x over previous
#include <cuda_runtime.h>
#include <cuda_bf16.h>

// SudokuDigitsDoubles — exact boolean reduction ("naked pairs" row elimination).
//
// Per (puzzle b, row r):
//   m[c]   = 9-bit candidate mask of cell c               (mask[b,d,r,c] > 0.5)
//   pv[c]  = m[c] if popcount(m[c]) == 2 else 0
//   active pattern p: appears exactly twice among pv[0..8]
//   erase[c] = OR of active patterns p with p != pv[c]
//   out bit (d,c) = m[c] & ~erase[c]
//
// Round 2: no float staging in smem. Only 9-bit masks (ints) round-trip
// through shared memory; input floats -> register masks -> row logic ->
// keep masks -> output floats, with all global accesses coalesced.

static constexpr int PUZ_ELEMS = 729;     // 9 digits * 81 cells
static constexpr int PUZ_PER_BLOCK = 8;
static constexpr int NMASK = PUZ_PER_BLOCK * 81;   // 648
static constexpr int THREADS = 256;

__global__ __launch_bounds__(THREADS)
void sudoku_doubles_kernel(const float* __restrict__ in,
                           float* __restrict__ out,
                           int nPuz)
{
    __shared__ int masks[NMASK];
    __shared__ int keepm[NMASK];

    const int basePuz = blockIdx.x * PUZ_PER_BLOCK;
    const int puzCount = min(PUZ_PER_BLOCK, nPuz - basePuz);
    const int nActive = puzCount * 81;

    // ---- Phase 1: build 9-bit candidate masks (coalesced LDG.32) ----
    #pragma unroll 1
    for (int j = threadIdx.x; j < nActive; j += THREADS) {
        const int pl = j / 81;          // local puzzle
        const int rc = j % 81;          // row*9 + col
        const float* p = in + (size_t)(basePuz + pl) * PUZ_ELEMS + rc;
        int mm = 0;
        #pragma unroll
        for (int d = 0; d < 9; d++)
            mm |= (p[d * 81] > 0.5f) ? (1 << d) : 0;
        masks[j] = mm;
    }
    __syncthreads();

    // ---- Phase 2: per-row naked-pair logic (72 threads, int-only) ----
    const int t = threadIdx.x;
    if (t < puzCount * 9) {
        const int pl = t / 9;
        const int r  = t % 9;
        const int rowBase = pl * 81 + r * 9;

        int m[9], pv[9];
        #pragma unroll
        for (int c = 0; c < 9; c++) {
            m[c]  = masks[rowBase + c];
            pv[c] = (__popc(m[c]) == 2) ? m[c] : 0;
        }

        int cnt[9];
        #pragma unroll
        for (int j = 0; j < 9; j++) {
            int cc = 0;
            #pragma unroll
            for (int k = 0; k < 9; k++)
                cc += (pv[k] == pv[j]) ? 1 : 0;
            cnt[j] = (pv[j] != 0) ? cc : 0;
        }

        #pragma unroll
        for (int c = 0; c < 9; c++) {
            int e = 0;
            #pragma unroll
            for (int j = 0; j < 9; j++)
                if (cnt[j] == 2 && pv[j] != pv[c]) e |= pv[j];
            keepm[rowBase + c] = m[c] & ~e;
        }
    }
    __syncthreads();

    // ---- Phase 3: expand keep masks to output floats (coalesced STG.32) ----
    #pragma unroll 1
    for (int j = threadIdx.x; j < nActive; j += THREADS) {
        const int pl = j / 81;
        const int rc = j % 81;
        const int k = keepm[j];
        float* p = out + (size_t)(basePuz + pl) * PUZ_ELEMS + rc;
        #pragma unroll
        for (int d = 0; d < 9; d++)
            p[d * 81] = (float)((k >> d) & 1);
    }
}

extern "C" void kernel_launch(void* const* d_in, const int* in_sizes, int n_in,
                              void* d_out, int out_size)
{
    const float* mask = (const float*)d_in[0];
    float* out = (float*)d_out;
    const int nPuz = in_sizes[0] / PUZ_ELEMS;   // 32768
    const int grid = (nPuz + PUZ_PER_BLOCK - 1) / PUZ_PER_BLOCK;
    sudoku_doubles_kernel<<<grid, THREADS>>>(mask, out, nPuz);
}